// round 12
// baseline (speedup 1.0000x reference)
#include <cuda_runtime.h>
#include <cstdint>

// CSR SpMM, sum-reduce: out[r,:] = sum_e value[e] * other[col[e],:]
// N_ROWS=100000, DEG=16 (fixed), F=64, fp32. rowptr/col INT32.
//
// Settled model (R3-R10): every design pins lts at 56-61% with L2%*dur ~17.4us
// invariant == the achievable path-independent LTS cap. The 410MB gather
// stream is irreducible (random columns, no capturable reuse). Remaining gap
// to the byte floor is wave/tail/setup overhead -> persistent CTAs:
// grid = ~SMs*6, each CTA grid-strides over 16-row blocks (R5 inner shape:
// 16 lanes/row, metadata pre-resident int4/float4, 4 gathers in flight).

static constexpr int F4 = 16;       // float4 groups per row (F=64)
static constexpr int ROWS_PER_BLK = 16;

__global__ __launch_bounds__(256, 6) void spmm_kernel(
    const int* __restrict__ rowptr,
    const int* __restrict__ col,
    const float* __restrict__ value,
    const float4* __restrict__ other,   // [N_COLS * 16] float4
    float4* __restrict__ out,           // [N_ROWS * 16] float4
    int n_rows, int n_blocks)
{
    const unsigned f = threadIdx.x;     // 0..15

    for (int blk = blockIdx.x; blk < n_blocks; blk += gridDim.x) {
        const int row = blk * ROWS_PER_BLK + threadIdx.y;
        if (row >= n_rows) continue;

        const int start = rowptr[row];
        const int deg   = rowptr[row + 1] - start;

        float4 acc = make_float4(0.f, 0.f, 0.f, 0.f);

        if (deg == 16 && (start & 3) == 0) {
            const int4*   c4 = (const int4*)(col + start);
            const float4* v4 = (const float4*)(value + start);

            // Metadata pre-resident (broadcast within 16-lane group).
            int4   c[4];
            float4 v[4];
#pragma unroll
            for (int b = 0; b < 4; ++b) {
                c[b] = __ldg(&c4[b]);
                v[b] = __ldg(&v4[b]);
            }

#pragma unroll
            for (int b = 0; b < 4; ++b) {
                // 32-bit offsets: max 99999*16+15 < 2^21.
                float4 x0 = __ldg(other + ((unsigned)c[b].x * 16u + f));
                float4 x1 = __ldg(other + ((unsigned)c[b].y * 16u + f));
                float4 x2 = __ldg(other + ((unsigned)c[b].z * 16u + f));
                float4 x3 = __ldg(other + ((unsigned)c[b].w * 16u + f));

                acc.x = fmaf(v[b].x, x0.x, acc.x);
                acc.y = fmaf(v[b].x, x0.y, acc.y);
                acc.z = fmaf(v[b].x, x0.z, acc.z);
                acc.w = fmaf(v[b].x, x0.w, acc.w);

                acc.x = fmaf(v[b].y, x1.x, acc.x);
                acc.y = fmaf(v[b].y, x1.y, acc.y);
                acc.z = fmaf(v[b].y, x1.z, acc.z);
                acc.w = fmaf(v[b].y, x1.w, acc.w);

                acc.x = fmaf(v[b].z, x2.x, acc.x);
                acc.y = fmaf(v[b].z, x2.y, acc.y);
                acc.z = fmaf(v[b].z, x2.z, acc.z);
                acc.w = fmaf(v[b].z, x2.w, acc.w);

                acc.x = fmaf(v[b].w, x3.x, acc.x);
                acc.y = fmaf(v[b].w, x3.y, acc.y);
                acc.z = fmaf(v[b].w, x3.z, acc.z);
                acc.w = fmaf(v[b].w, x3.w, acc.w);
            }
        } else {
            for (int e = start; e < start + deg; ++e) {
                const int   c = __ldg(&col[e]);
                const float v = __ldg(&value[e]);
                const float4 x = __ldg(&other[(unsigned)c * 16u + f]);
                acc.x = fmaf(v, x.x, acc.x);
                acc.y = fmaf(v, x.y, acc.y);
                acc.z = fmaf(v, x.z, acc.z);
                acc.w = fmaf(v, x.w, acc.w);
            }
        }

        out[(unsigned)row * 16u + f] = acc;
    }
}

extern "C" void kernel_launch(void* const* d_in, const int* in_sizes, int n_in,
                              void* d_out, int out_size)
{
    // metadata order: rowptr (int32, N_ROWS+1), col (int32, E), value (f32, E), other (f32, N_COLS*F)
    const int*    rowptr = (const int*)d_in[0];
    const int*    col    = (const int*)d_in[1];
    const float*  value  = (const float*)d_in[2];
    const float4* other  = (const float4*)d_in[3];
    float4*       out    = (float4*)d_out;

    const int n_rows   = in_sizes[0] - 1;
    const int n_blocks = (n_rows + ROWS_PER_BLK - 1) / ROWS_PER_BLK;

    // Persistent grid: ~6 CTAs per SM (GB300 = 152 SMs). Capped by work.
    int grid = 152 * 6;
    if (grid > n_blocks) grid = n_blocks;

    dim3 block(F4, ROWS_PER_BLK);
    spmm_kernel<<<grid, block>>>(rowptr, col, value, other, out, n_rows, n_blocks);
}

// round 13
// speedup vs baseline: 1.5357x; 1.5357x over previous
#include <cuda_runtime.h>
#include <cstdint>

// CSR SpMM, sum-reduce: out[r,:] = sum_e value[e] * other[col[e],:]
// N_ROWS=100000, DEG=16 (fixed), F=64, fp32. rowptr/col INT32.
//
// FINAL (= R5, best measured 26.85us). Settled model: kernel sits on the
// chip's achievable LTS gather rate (L2% x dur ~= 17.4us invariant across
// 5 distinct designs at occ 32-87%, MLP 2-8, L1-alloc vs L2-only, persistent
// vs waved). 410MB of random 256B row gathers is irreducible traffic; all
// structural levers measured neutral-or-worse. R11 (persistent) doubled
// L1tex wavefront work -> reverted.
//
// Shape: 16 lanes per output row, each lane owns one float4 of F=64.
// blockDim=(16,16). Per edge: 16 lanes x 16B = one contiguous 256B row of
// `other`. Metadata (col/value) pre-resident via broadcast int4/float4 loads;
// gathers issued in 4 batches of 4 independent LDG.E.128 (batches overlap
// since all indices are pre-loaded). launch_bounds(256,5) -> regs 48, ~40w/SM.

static constexpr int F4 = 16;       // float4 groups per row (F=64)
static constexpr int ROWS_PER_BLK = 16;

__global__ __launch_bounds__(256, 5) void spmm_kernel(
    const int* __restrict__ rowptr,
    const int* __restrict__ col,
    const float* __restrict__ value,
    const float4* __restrict__ other,   // [N_COLS * 16] float4
    float4* __restrict__ out,           // [N_ROWS * 16] float4
    int n_rows)
{
    const int row = blockIdx.x * ROWS_PER_BLK + threadIdx.y;
    if (row >= n_rows) return;
    const int f = threadIdx.x;          // 0..15

    const int start = rowptr[row];
    const int deg   = rowptr[row + 1] - start;

    float4 acc = make_float4(0.f, 0.f, 0.f, 0.f);

    if (deg == 16 && (start & 3) == 0) {
        // Vectorized metadata: 4x int4 + 4x float4 (64B-aligned since start%4==0).
        const int4*   c4 = (const int4*)(col + start);
        const float4* v4 = (const float4*)(value + start);

        int4   c[4];
        float4 v[4];
#pragma unroll
        for (int b = 0; b < 4; ++b) {
            c[b] = __ldg(&c4[b]);
            v[b] = __ldg(&v4[b]);
        }

        // 4 batches of 4 independent gathers; batch b+1 gathers depend only on
        // pre-resident indices, so they overlap batch b's scoreboard wait.
#pragma unroll
        for (int b = 0; b < 4; ++b) {
            float4 x0 = __ldg(&other[(long long)c[b].x * F4 + f]);
            float4 x1 = __ldg(&other[(long long)c[b].y * F4 + f]);
            float4 x2 = __ldg(&other[(long long)c[b].z * F4 + f]);
            float4 x3 = __ldg(&other[(long long)c[b].w * F4 + f]);

            acc.x = fmaf(v[b].x, x0.x, acc.x);
            acc.y = fmaf(v[b].x, x0.y, acc.y);
            acc.z = fmaf(v[b].x, x0.z, acc.z);
            acc.w = fmaf(v[b].x, x0.w, acc.w);

            acc.x = fmaf(v[b].y, x1.x, acc.x);
            acc.y = fmaf(v[b].y, x1.y, acc.y);
            acc.z = fmaf(v[b].y, x1.z, acc.z);
            acc.w = fmaf(v[b].y, x1.w, acc.w);

            acc.x = fmaf(v[b].z, x2.x, acc.x);
            acc.y = fmaf(v[b].z, x2.y, acc.y);
            acc.z = fmaf(v[b].z, x2.z, acc.z);
            acc.w = fmaf(v[b].z, x2.w, acc.w);

            acc.x = fmaf(v[b].w, x3.x, acc.x);
            acc.y = fmaf(v[b].w, x3.y, acc.y);
            acc.z = fmaf(v[b].w, x3.z, acc.z);
            acc.w = fmaf(v[b].w, x3.w, acc.w);
        }
    } else {
        for (int e = start; e < start + deg; ++e) {
            const int   c = __ldg(&col[e]);
            const float v = __ldg(&value[e]);
            const float4 x = __ldg(&other[(long long)c * F4 + f]);
            acc.x = fmaf(v, x.x, acc.x);
            acc.y = fmaf(v, x.y, acc.y);
            acc.z = fmaf(v, x.z, acc.z);
            acc.w = fmaf(v, x.w, acc.w);
        }
    }

    out[(long long)row * F4 + f] = acc;
}

extern "C" void kernel_launch(void* const* d_in, const int* in_sizes, int n_in,
                              void* d_out, int out_size)
{
    // metadata order: rowptr (int32, N_ROWS+1), col (int32, E), value (f32, E), other (f32, N_COLS*F)
    const int*    rowptr = (const int*)d_in[0];
    const int*    col    = (const int*)d_in[1];
    const float*  value  = (const float*)d_in[2];
    const float4* other  = (const float4*)d_in[3];
    float4*       out    = (float4*)d_out;

    const int n_rows = in_sizes[0] - 1;

    dim3 block(F4, ROWS_PER_BLK);
    dim3 grid((n_rows + ROWS_PER_BLK - 1) / ROWS_PER_BLK);
    spmm_kernel<<<grid, block>>>(rowptr, col, value, other, out, n_rows);
}

// round 14
// speedup vs baseline: 1.5502x; 1.0094x over previous
#include <cuda_runtime.h>
#include <cstdint>

// CSR SpMM, sum-reduce: out[r,:] = sum_e value[e] * other[col[e],:]
// N_ROWS=100000, DEG=16 (fixed), F=64, fp32. rowptr/col INT32.
//
// FINAL — frozen at the measured roofline. Six designs (occ 32-87%, MLP 2-8,
// L1-alloc vs L2-only, waved vs persistent) all land 26.8-27.4us with absolute
// L2 throughput invariant (~16-17 TB/s; L2% x dur ~= 17.4us every profile):
// the random-gather path is the hardware wall. Traffic (410MB of random 256B
// row gathers) is irreducible: ~0.9% L1 reuse capture, no intra-CTA dups,
// column-major scatter would cost ~280us of LTS atomics, TMA/LDGSTS share the
// same path-independent LTS cap.
//
// Shape: 16 lanes per output row, each lane owns one float4 of F=64.
// blockDim=(16,16), 6250 CTAs (no tail: 100000 = 6250*16). Per edge: 16 lanes
// x 16B = one contiguous 256B row of `other`. Metadata pre-resident via
// broadcast int4/float4 loads; gathers in 4 batches of 4 independent
// LDG.E.128 (batches overlap — indices all pre-loaded). launch_bounds(256,5).

static constexpr int F4 = 16;       // float4 groups per row (F=64)
static constexpr int ROWS_PER_BLK = 16;

__global__ __launch_bounds__(256, 5) void spmm_kernel(
    const int* __restrict__ rowptr,
    const int* __restrict__ col,
    const float* __restrict__ value,
    const float4* __restrict__ other,   // [N_COLS * 16] float4
    float4* __restrict__ out,           // [N_ROWS * 16] float4
    int n_rows)
{
    const int row = blockIdx.x * ROWS_PER_BLK + threadIdx.y;
    if (row >= n_rows) return;
    const int f = threadIdx.x;          // 0..15

    const int start = rowptr[row];
    const int deg   = rowptr[row + 1] - start;

    float4 acc = make_float4(0.f, 0.f, 0.f, 0.f);

    if (deg == 16 && (start & 3) == 0) {
        // Vectorized metadata: 4x int4 + 4x float4 (64B-aligned since start%4==0).
        const int4*   c4 = (const int4*)(col + start);
        const float4* v4 = (const float4*)(value + start);

        int4   c[4];
        float4 v[4];
#pragma unroll
        for (int b = 0; b < 4; ++b) {
            c[b] = __ldg(&c4[b]);
            v[b] = __ldg(&v4[b]);
        }

        // 4 batches of 4 independent gathers; batch b+1 gathers depend only on
        // pre-resident indices, so they overlap batch b's scoreboard wait.
#pragma unroll
        for (int b = 0; b < 4; ++b) {
            float4 x0 = __ldg(&other[(long long)c[b].x * F4 + f]);
            float4 x1 = __ldg(&other[(long long)c[b].y * F4 + f]);
            float4 x2 = __ldg(&other[(long long)c[b].z * F4 + f]);
            float4 x3 = __ldg(&other[(long long)c[b].w * F4 + f]);

            acc.x = fmaf(v[b].x, x0.x, acc.x);
            acc.y = fmaf(v[b].x, x0.y, acc.y);
            acc.z = fmaf(v[b].x, x0.z, acc.z);
            acc.w = fmaf(v[b].x, x0.w, acc.w);

            acc.x = fmaf(v[b].y, x1.x, acc.x);
            acc.y = fmaf(v[b].y, x1.y, acc.y);
            acc.z = fmaf(v[b].y, x1.z, acc.z);
            acc.w = fmaf(v[b].y, x1.w, acc.w);

            acc.x = fmaf(v[b].z, x2.x, acc.x);
            acc.y = fmaf(v[b].z, x2.y, acc.y);
            acc.z = fmaf(v[b].z, x2.z, acc.z);
            acc.w = fmaf(v[b].z, x2.w, acc.w);

            acc.x = fmaf(v[b].w, x3.x, acc.x);
            acc.y = fmaf(v[b].w, x3.y, acc.y);
            acc.z = fmaf(v[b].w, x3.z, acc.z);
            acc.w = fmaf(v[b].w, x3.w, acc.w);
        }
    } else {
        for (int e = start; e < start + deg; ++e) {
            const int   c = __ldg(&col[e]);
            const float v = __ldg(&value[e]);
            const float4 x = __ldg(&other[(long long)c * F4 + f]);
            acc.x = fmaf(v, x.x, acc.x);
            acc.y = fmaf(v, x.y, acc.y);
            acc.z = fmaf(v, x.z, acc.z);
            acc.w = fmaf(v, x.w, acc.w);
        }
    }

    out[(long long)row * F4 + f] = acc;
}

extern "C" void kernel_launch(void* const* d_in, const int* in_sizes, int n_in,
                              void* d_out, int out_size)
{
    // metadata order: rowptr (int32, N_ROWS+1), col (int32, E), value (f32, E), other (f32, N_COLS*F)
    const int*    rowptr = (const int*)d_in[0];
    const int*    col    = (const int*)d_in[1];
    const float*  value  = (const float*)d_in[2];
    const float4* other  = (const float4*)d_in[3];
    float4*       out    = (float4*)d_out;

    const int n_rows = in_sizes[0] - 1;

    dim3 block(F4, ROWS_PER_BLK);
    dim3 grid((n_rows + ROWS_PER_BLK - 1) / ROWS_PER_BLK);
    spmm_kernel<<<grid, block>>>(rowptr, col, value, other, out, n_rows);
}